// round 13
// baseline (speedup 1.0000x reference)
#include <cuda_runtime.h>
#include <cuda_bf16.h>
#include <cstdint>
#include <cstddef>

// Problem dims (fixed)
#define T_STEPS 100
#define BATCH   256
#define IN_DIM  784
#define HID     1024
#define OUT_DIM 10
#define MROWS   25600
#define BH      262144
#define BO      2560
#define HID_OUT ((size_t)MROWS * HID)
#define THRESH 0.9f
#define DECAY  0.6f

// GEMM1 tiling: 128x128 CTA tile, BK=16, 49 k-iters, 7-stage cp.async ring
#define NKIT 49
#define NSTAGE 7
#define A_STAGE_B 6144u     // 128 rows * 24 bf16 (48B, padded)
#define B_PLANE_B 4352u     // 16 rows * 136 bf16 (272B, padded)
#define STAGE_B  14848u     // A + 2 B planes
#define SMEM_TOTAL (NSTAGE * STAGE_B)   // 103936 -> 2 CTAs/SM (207.9KB)

// ------------------------- scratch (device globals) -----------------------
__device__ __nv_bfloat16 g_Xbf[(size_t)MROWS * IN_DIM];        // 40.1 MB
__device__ __nv_bfloat16 g_W1c[(size_t)2 * IN_DIM * HID];      // hi rows 0..783, lo rows 784..1567
__device__ float         g_U1[(size_t)MROWS * HID];            // 104.9 MB
__device__ float         g_U2[(size_t)MROWS * OUT_DIM];        // 1.0 MB

// ------------------------- helpers ---------------------------------------
__device__ __forceinline__ uint32_t smem_u32(const void* p) {
    uint32_t a;
    asm("{ .reg .u64 t; cvta.to.shared.u64 t, %1; cvt.u32.u64 %0, t; }" : "=r"(a) : "l"(p));
    return a;
}
__device__ __forceinline__ void cpa16(uint32_t s, const void* g) {
    asm volatile("cp.async.cg.shared.global [%0], [%1], 16;\n" :: "r"(s), "l"(g));
}
__device__ __forceinline__ void ldsm_x4(uint32_t& r0, uint32_t& r1, uint32_t& r2, uint32_t& r3, uint32_t addr) {
    asm volatile("ldmatrix.sync.aligned.m8n8.x4.shared.b16 {%0,%1,%2,%3}, [%4];\n"
                 : "=r"(r0), "=r"(r1), "=r"(r2), "=r"(r3) : "r"(addr));
}
__device__ __forceinline__ void ldsm_x4_t(uint32_t& r0, uint32_t& r1, uint32_t& r2, uint32_t& r3, uint32_t addr) {
    asm volatile("ldmatrix.sync.aligned.m8n8.x4.trans.shared.b16 {%0,%1,%2,%3}, [%4];\n"
                 : "=r"(r0), "=r"(r1), "=r"(r2), "=r"(r3) : "r"(addr));
}
__device__ __forceinline__ void mma16816(float* c, const uint32_t* a, uint32_t b0, uint32_t b1) {
    asm volatile(
        "mma.sync.aligned.m16n8k16.row.col.f32.bf16.bf16.f32 "
        "{%0,%1,%2,%3}, {%4,%5,%6,%7}, {%8,%9}, {%0,%1,%2,%3};\n"
        : "+f"(c[0]), "+f"(c[1]), "+f"(c[2]), "+f"(c[3])
        : "r"(a[0]), "r"(a[1]), "r"(a[2]), "r"(a[3]), "r"(b0), "r"(b1));
}

// ------------------------- fused prep kernel -------------------------------
#define PREPX_BLKS 19600
#define PREPW_BLKS 3136
#define ZERO_BLKS  250
__global__ void prep_kernel(const float4* __restrict__ x, const float* __restrict__ w1) {
    const int bid = blockIdx.x;
    if (bid < PREPX_BLKS) {
        int i = bid * 256 + threadIdx.x;                  // < 5,017,600
        float4 v = x[i];
        __nv_bfloat162* dst = reinterpret_cast<__nv_bfloat162*>(g_Xbf);
        dst[2 * i]     = __floats2bfloat162_rn(v.x, v.y);
        dst[2 * i + 1] = __floats2bfloat162_rn(v.z, v.w);
    } else if (bid < PREPX_BLKS + PREPW_BLKS) {
        int i = (bid - PREPX_BLKS) * 256 + threadIdx.x;   // < 802816
        float w = w1[i];
        __nv_bfloat16 hi = __float2bfloat16(w);
        __nv_bfloat16 lo = __float2bfloat16(w - __bfloat162float(hi));
        g_W1c[i] = hi;
        g_W1c[802816 + i] = lo;
    } else {
        int i = (bid - PREPX_BLKS - PREPW_BLKS) * 256 + threadIdx.x;  // < 64000
        reinterpret_cast<float4*>(g_U2)[i] = make_float4(0.f, 0.f, 0.f, 0.f);
    }
}

// ------------------------- GEMM1: U1 = X @ (W1hi + W1lo) ------------------
// 8 warps (2x4), warp tile 64x32, fp32 accum; hi/lo passes share the A tile.
__global__ __launch_bounds__(256, 2) void gemm1_kernel() {
    extern __shared__ char smem[];
    const uint32_t sbase = smem_u32(smem);

    const int tid = threadIdx.x;
    const int bn0 = blockIdx.x * 128;
    const int bm0 = blockIdx.y * 128;

    const int lane   = tid & 31;
    const int wid    = tid >> 5;
    const int warp_m = wid >> 2;   // 0..1
    const int warp_n = wid & 3;    // 0..3

    float acc[4][4][4];
#pragma unroll
    for (int i = 0; i < 4; i++)
#pragma unroll
        for (int j = 0; j < 4; j++)
#pragma unroll
            for (int k = 0; k < 4; k++) acc[i][j][k] = 0.0f;

    // producer addressing
    const int arow = tid >> 1, ach = tid & 1;
    const __nv_bfloat16* agp = g_Xbf + (size_t)(bm0 + arow) * IN_DIM + ach * 8;
    const int brow = tid >> 4, bch = tid & 15;
    const __nv_bfloat16* bgp = g_W1c + (size_t)brow * HID + bn0 + bch * 8;

    const uint32_t a_dst = sbase + arow * 48 + ach * 16;
    const uint32_t b_dst = sbase + A_STAGE_B + brow * 272 + bch * 16;

#define LOAD_STAGE(slot, kt) do {                                                   \
        uint32_t so = (slot) * STAGE_B;                                             \
        const __nv_bfloat16* a = agp + (size_t)(kt) * 16;                           \
        const __nv_bfloat16* b = bgp + (size_t)(kt) * 16 * HID;                     \
        cpa16(a_dst + so, a);                                                       \
        cpa16(b_dst + so, b);                                                       \
        cpa16(b_dst + so + B_PLANE_B, b + 802816);                                  \
        asm volatile("cp.async.commit_group;\n" ::: "memory");                      \
    } while (0)

    LOAD_STAGE(0, 0);
    LOAD_STAGE(1, 1);
    LOAD_STAGE(2, 2);
    LOAD_STAGE(3, 3);
    LOAD_STAGE(4, 4);
    LOAD_STAGE(5, 5);

    for (int kt = 0; kt < NKIT; kt++) {
        const int cur = kt % NSTAGE;
        asm volatile("cp.async.wait_group 5;\n" ::: "memory");
        __syncthreads();

        // prefetch 6 ahead into the slot consumed last iteration
        if (kt + 6 < NKIT) {
            LOAD_STAGE((kt + 6) % NSTAGE, kt + 6);
        } else {
            asm volatile("cp.async.commit_group;\n" ::: "memory");
        }

        const uint32_t so = sbase + cur * STAGE_B;

        // A fragments (shared by hi/lo passes)
        uint32_t a[4][4];
#pragma unroll
        for (int mt = 0; mt < 4; mt++) {
            int row = warp_m * 64 + mt * 16 + (lane & 15);
            uint32_t addr = so + row * 48 + (lane >> 4) * 16;
            ldsm_x4(a[mt][0], a[mt][1], a[mt][2], a[mt][3], addr);
        }
#pragma unroll
        for (int p = 0; p < 2; p++) {
            // hoist both B ldsm of this pass before the 16 MMAs
            uint32_t b[2][4];
#pragma unroll
            for (int nt = 0; nt < 2; nt++) {
                int krow = lane & 15;
                int col  = warp_n * 32 + nt * 16 + (lane >> 4) * 8;
                uint32_t addr = so + A_STAGE_B + p * B_PLANE_B + krow * 272 + col * 2;
                ldsm_x4_t(b[nt][0], b[nt][1], b[nt][2], b[nt][3], addr);
            }
#pragma unroll
            for (int nt = 0; nt < 2; nt++) {
#pragma unroll
                for (int mt = 0; mt < 4; mt++) {
                    mma16816(acc[mt][nt * 2],     a[mt], b[nt][0], b[nt][1]);
                    mma16816(acc[mt][nt * 2 + 1], a[mt], b[nt][2], b[nt][3]);
                }
            }
        }
    }
#undef LOAD_STAGE

    // epilogue: write U1 (fp32)
    const int g  = lane >> 2;
    const int tg = lane & 3;
#pragma unroll
    for (int mt = 0; mt < 4; mt++) {
        int m0 = bm0 + warp_m * 64 + mt * 16 + g;
#pragma unroll
        for (int nf = 0; nf < 4; nf++) {
            int n0 = bn0 + warp_n * 32 + nf * 8 + tg * 2;
            float2 v0 = make_float2(acc[mt][nf][0], acc[mt][nf][1]);
            float2 v1 = make_float2(acc[mt][nf][2], acc[mt][nf][3]);
            *(float2*)&g_U1[(size_t)m0 * HID + n0]       = v0;
            *(float2*)&g_U1[(size_t)(m0 + 8) * HID + n0] = v1;
        }
    }
}

// ---------------- scan1: LIF hidden + fused sparse GEMM2 ------------------
// One thread per 8 (b,h) lanes (2 float4); 1-deep prefetch -> MLP 4.
// On the (rare) spike, scatter W2 row into U2.
__global__ void scan1_kernel(float4* __restrict__ out, const float* __restrict__ W2) {
    const int idx = blockIdx.x * blockDim.x + threadIdx.x;   // 0..32767
    const float4* u = reinterpret_cast<const float4*>(g_U1);
    const int c0 = idx * 2;            // first float4 column
    const int j0 = idx * 8;
    const int b  = j0 >> 10;
    const int h0 = j0 & 1023;
    float4 mem0 = make_float4(0.f, 0.f, 0.f, 0.f);
    float4 mem1 = make_float4(0.f, 0.f, 0.f, 0.f);
    float4 p0 = __ldcg(&u[c0]);
    float4 p1 = __ldcg(&u[c0 + 1]);
#pragma unroll 4
    for (int t = 0; t < T_STEPS; t++) {
        float4 v0 = p0, v1 = p1;
        if (t + 1 < T_STEPS) {
            p0 = __ldcg(&u[(size_t)(t + 1) * (BH / 4) + c0]);
            p1 = __ldcg(&u[(size_t)(t + 1) * (BH / 4) + c0 + 1]);
        }
        float4 s0, s1;
        mem0.x = mem0.x * DECAY + v0.x; s0.x = (mem0.x >= THRESH) ? 1.f : 0.f; mem0.x -= s0.x * THRESH;
        mem0.y = mem0.y * DECAY + v0.y; s0.y = (mem0.y >= THRESH) ? 1.f : 0.f; mem0.y -= s0.y * THRESH;
        mem0.z = mem0.z * DECAY + v0.z; s0.z = (mem0.z >= THRESH) ? 1.f : 0.f; mem0.z -= s0.z * THRESH;
        mem0.w = mem0.w * DECAY + v0.w; s0.w = (mem0.w >= THRESH) ? 1.f : 0.f; mem0.w -= s0.w * THRESH;
        mem1.x = mem1.x * DECAY + v1.x; s1.x = (mem1.x >= THRESH) ? 1.f : 0.f; mem1.x -= s1.x * THRESH;
        mem1.y = mem1.y * DECAY + v1.y; s1.y = (mem1.y >= THRESH) ? 1.f : 0.f; mem1.y -= s1.y * THRESH;
        mem1.z = mem1.z * DECAY + v1.z; s1.z = (mem1.z >= THRESH) ? 1.f : 0.f; mem1.z -= s1.z * THRESH;
        mem1.w = mem1.w * DECAY + v1.w; s1.w = (mem1.w >= THRESH) ? 1.f : 0.f; mem1.w -= s1.w * THRESH;
        out[(size_t)t * (BH / 4) + c0]     = s0;
        out[(size_t)t * (BH / 4) + c0 + 1] = s1;
        float ssum = s0.x + s0.y + s0.z + s0.w + s1.x + s1.y + s1.z + s1.w;
        if (ssum > 0.f) {                                   // rare (~1900 spikes total)
            float sv[8] = {s0.x, s0.y, s0.z, s0.w, s1.x, s1.y, s1.z, s1.w};
            float* u2 = g_U2 + (size_t)(t * BATCH + b) * OUT_DIM;
#pragma unroll
            for (int q = 0; q < 8; q++) {
                if (sv[q] != 0.f) {
                    const float* w = W2 + (h0 + q) * OUT_DIM;
#pragma unroll
                    for (int o = 0; o < OUT_DIM; o++) atomicAdd(&u2[o], w[o]);
                }
            }
        }
    }
}

// ------------------------- scan2: cooperatively staged LIF output ---------
// 20 blocks x 512 threads; ALL 512 threads stage the [100][128] U2 slice
// (25 fully parallel coalesced loads each), then 128 threads scan from smem.
__global__ void scan2_kernel(float* __restrict__ out2) {
    extern __shared__ float sm[];                 // [100][128]
    const int tid = threadIdx.x;
    const int lane0 = blockIdx.x * 128;
#pragma unroll
    for (int i = tid; i < T_STEPS * 128; i += 512) {
        int t = i >> 7, lane = i & 127;
        sm[i] = g_U2[(size_t)t * BO + lane0 + lane];
    }
    __syncthreads();
    if (tid < 128) {
        float mem = 0.0f;
#pragma unroll 5
        for (int t = 0; t < T_STEPS; t++) {
            float u = sm[t * 128 + tid];
            mem = mem * DECAY + u;
            float s = (mem >= THRESH) ? 1.0f : 0.0f;
            mem -= s * THRESH;
            out2[(size_t)t * BO + lane0 + tid] = s;
        }
    }
}

// ------------------------- launch ------------------------------------------
extern "C" void kernel_launch(void* const* d_in, const int* in_sizes, int n_in,
                              void* d_out, int out_size) {
    const float* X  = (const float*)d_in[0];
    const float* W1 = (const float*)d_in[1];
    const float* W2 = (const float*)d_in[2];
    float* out = (float*)d_out;
    (void)in_sizes; (void)n_in; (void)out_size;

    static bool attr_done = false;
    if (!attr_done) {
        cudaFuncSetAttribute(gemm1_kernel, cudaFuncAttributeMaxDynamicSharedMemorySize, SMEM_TOTAL);
        cudaFuncSetAttribute(scan2_kernel, cudaFuncAttributeMaxDynamicSharedMemorySize, 51200);
        attr_done = true;
    }

    prep_kernel<<<PREPX_BLKS + PREPW_BLKS + ZERO_BLKS, 256>>>((const float4*)X, W1);

    gemm1_kernel<<<dim3(8, 200), 256, SMEM_TOTAL>>>();

    scan1_kernel<<<64, 512>>>((float4*)out, W2);

    scan2_kernel<<<20, 512, 51200>>>(out + HID_OUT);
}

// round 14
// speedup vs baseline: 1.0362x; 1.0362x over previous
#include <cuda_runtime.h>
#include <cuda_bf16.h>
#include <cstdint>
#include <cstddef>

// Problem dims (fixed)
#define T_STEPS 100
#define BATCH   256
#define IN_DIM  784
#define HID     1024
#define OUT_DIM 10
#define MROWS   25600
#define BH      262144
#define BO      2560
#define HID_OUT ((size_t)MROWS * HID)
#define THRESH 0.9f
#define DECAY  0.6f

// GEMM1 tiling: 128x128 CTA tile, BK=16, 49 k-iters, 7-stage cp.async ring
#define NKIT 49
#define NSTAGE 7
#define A_STAGE_B 6144u     // 128 rows * 24 bf16 (48B, padded)
#define B_PLANE_B 4352u     // 16 rows * 136 bf16 (272B, padded)
#define STAGE_B  14848u     // A + 2 B planes
#define SMEM_TOTAL (NSTAGE * STAGE_B)   // 103936 -> 2 CTAs/SM (207.9KB)

// ------------------------- scratch (device globals) -----------------------
__device__ __nv_bfloat16 g_Xbf[(size_t)MROWS * IN_DIM];        // 40.1 MB
__device__ __nv_bfloat16 g_W1c[(size_t)2 * IN_DIM * HID];      // hi rows 0..783, lo rows 784..1567
__device__ float         g_U1[(size_t)MROWS * HID];            // 104.9 MB
__device__ float         g_U2[(size_t)MROWS * OUT_DIM];        // 1.0 MB

// ------------------------- helpers ---------------------------------------
__device__ __forceinline__ uint32_t smem_u32(const void* p) {
    uint32_t a;
    asm("{ .reg .u64 t; cvta.to.shared.u64 t, %1; cvt.u32.u64 %0, t; }" : "=r"(a) : "l"(p));
    return a;
}
__device__ __forceinline__ void cpa16(uint32_t s, const void* g) {
    asm volatile("cp.async.cg.shared.global [%0], [%1], 16;\n" :: "r"(s), "l"(g));
}
__device__ __forceinline__ void ldsm_x4(uint32_t& r0, uint32_t& r1, uint32_t& r2, uint32_t& r3, uint32_t addr) {
    asm volatile("ldmatrix.sync.aligned.m8n8.x4.shared.b16 {%0,%1,%2,%3}, [%4];\n"
                 : "=r"(r0), "=r"(r1), "=r"(r2), "=r"(r3) : "r"(addr));
}
__device__ __forceinline__ void ldsm_x4_t(uint32_t& r0, uint32_t& r1, uint32_t& r2, uint32_t& r3, uint32_t addr) {
    asm volatile("ldmatrix.sync.aligned.m8n8.x4.trans.shared.b16 {%0,%1,%2,%3}, [%4];\n"
                 : "=r"(r0), "=r"(r1), "=r"(r2), "=r"(r3) : "r"(addr));
}
__device__ __forceinline__ void mma16816(float* c, const uint32_t* a, uint32_t b0, uint32_t b1) {
    asm volatile(
        "mma.sync.aligned.m16n8k16.row.col.f32.bf16.bf16.f32 "
        "{%0,%1,%2,%3}, {%4,%5,%6,%7}, {%8,%9}, {%0,%1,%2,%3};\n"
        : "+f"(c[0]), "+f"(c[1]), "+f"(c[2]), "+f"(c[3])
        : "r"(a[0]), "r"(a[1]), "r"(a[2]), "r"(a[3]), "r"(b0), "r"(b1));
}

// ------------------------- fused prep kernel -------------------------------
#define PREPX_BLKS 19600
#define PREPW_BLKS 3136
#define ZERO_BLKS  250
__global__ void prep_kernel(const float4* __restrict__ x, const float* __restrict__ w1) {
    const int bid = blockIdx.x;
    if (bid < PREPX_BLKS) {
        int i = bid * 256 + threadIdx.x;                  // < 5,017,600
        float4 v = x[i];
        __nv_bfloat162* dst = reinterpret_cast<__nv_bfloat162*>(g_Xbf);
        dst[2 * i]     = __floats2bfloat162_rn(v.x, v.y);
        dst[2 * i + 1] = __floats2bfloat162_rn(v.z, v.w);
    } else if (bid < PREPX_BLKS + PREPW_BLKS) {
        int i = (bid - PREPX_BLKS) * 256 + threadIdx.x;   // < 802816
        float w = w1[i];
        __nv_bfloat16 hi = __float2bfloat16(w);
        __nv_bfloat16 lo = __float2bfloat16(w - __bfloat162float(hi));
        g_W1c[i] = hi;
        g_W1c[802816 + i] = lo;
    } else {
        int i = (bid - PREPX_BLKS - PREPW_BLKS) * 256 + threadIdx.x;  // < 64000
        reinterpret_cast<float4*>(g_U2)[i] = make_float4(0.f, 0.f, 0.f, 0.f);
    }
}

// ------------------------- GEMM1: U1 = X @ (W1hi + W1lo) ------------------
// 8 warps (2x4), warp tile 64x32, fp32 accum; hi/lo passes share the A tile.
__global__ __launch_bounds__(256, 2) void gemm1_kernel() {
    extern __shared__ char smem[];
    const uint32_t sbase = smem_u32(smem);

    const int tid = threadIdx.x;
    const int bn0 = blockIdx.x * 128;
    const int bm0 = blockIdx.y * 128;

    const int lane   = tid & 31;
    const int wid    = tid >> 5;
    const int warp_m = wid >> 2;   // 0..1
    const int warp_n = wid & 3;    // 0..3

    float acc[4][4][4];
#pragma unroll
    for (int i = 0; i < 4; i++)
#pragma unroll
        for (int j = 0; j < 4; j++)
#pragma unroll
            for (int k = 0; k < 4; k++) acc[i][j][k] = 0.0f;

    // producer addressing
    const int arow = tid >> 1, ach = tid & 1;
    const __nv_bfloat16* agp = g_Xbf + (size_t)(bm0 + arow) * IN_DIM + ach * 8;
    const int brow = tid >> 4, bch = tid & 15;
    const __nv_bfloat16* bgp = g_W1c + (size_t)brow * HID + bn0 + bch * 8;

    const uint32_t a_dst = sbase + arow * 48 + ach * 16;
    const uint32_t b_dst = sbase + A_STAGE_B + brow * 272 + bch * 16;

#define LOAD_STAGE(slot, kt) do {                                                   \
        uint32_t so = (slot) * STAGE_B;                                             \
        const __nv_bfloat16* a = agp + (size_t)(kt) * 16;                           \
        const __nv_bfloat16* b = bgp + (size_t)(kt) * 16 * HID;                     \
        cpa16(a_dst + so, a);                                                       \
        cpa16(b_dst + so, b);                                                       \
        cpa16(b_dst + so + B_PLANE_B, b + 802816);                                  \
        asm volatile("cp.async.commit_group;\n" ::: "memory");                      \
    } while (0)

    LOAD_STAGE(0, 0);
    LOAD_STAGE(1, 1);
    LOAD_STAGE(2, 2);
    LOAD_STAGE(3, 3);
    LOAD_STAGE(4, 4);
    LOAD_STAGE(5, 5);

    for (int kt = 0; kt < NKIT; kt++) {
        const int cur = kt % NSTAGE;
        asm volatile("cp.async.wait_group 5;\n" ::: "memory");
        __syncthreads();

        // prefetch 6 ahead into the slot consumed last iteration
        if (kt + 6 < NKIT) {
            LOAD_STAGE((kt + 6) % NSTAGE, kt + 6);
        } else {
            asm volatile("cp.async.commit_group;\n" ::: "memory");
        }

        const uint32_t so = sbase + cur * STAGE_B;

        // A fragments (shared by hi/lo passes)
        uint32_t a[4][4];
#pragma unroll
        for (int mt = 0; mt < 4; mt++) {
            int row = warp_m * 64 + mt * 16 + (lane & 15);
            uint32_t addr = so + row * 48 + (lane >> 4) * 16;
            ldsm_x4(a[mt][0], a[mt][1], a[mt][2], a[mt][3], addr);
        }
#pragma unroll
        for (int p = 0; p < 2; p++) {
            // hoist both B ldsm of this pass before the 16 MMAs
            uint32_t b[2][4];
#pragma unroll
            for (int nt = 0; nt < 2; nt++) {
                int krow = lane & 15;
                int col  = warp_n * 32 + nt * 16 + (lane >> 4) * 8;
                uint32_t addr = so + A_STAGE_B + p * B_PLANE_B + krow * 272 + col * 2;
                ldsm_x4_t(b[nt][0], b[nt][1], b[nt][2], b[nt][3], addr);
            }
#pragma unroll
            for (int nt = 0; nt < 2; nt++) {
#pragma unroll
                for (int mt = 0; mt < 4; mt++) {
                    mma16816(acc[mt][nt * 2],     a[mt], b[nt][0], b[nt][1]);
                    mma16816(acc[mt][nt * 2 + 1], a[mt], b[nt][2], b[nt][3]);
                }
            }
        }
    }
#undef LOAD_STAGE

    // epilogue: write U1 (fp32)
    const int g  = lane >> 2;
    const int tg = lane & 3;
#pragma unroll
    for (int mt = 0; mt < 4; mt++) {
        int m0 = bm0 + warp_m * 64 + mt * 16 + g;
#pragma unroll
        for (int nf = 0; nf < 4; nf++) {
            int n0 = bn0 + warp_n * 32 + nf * 8 + tg * 2;
            float2 v0 = make_float2(acc[mt][nf][0], acc[mt][nf][1]);
            float2 v1 = make_float2(acc[mt][nf][2], acc[mt][nf][3]);
            *(float2*)&g_U1[(size_t)m0 * HID + n0]       = v0;
            *(float2*)&g_U1[(size_t)(m0 + 8) * HID + n0] = v1;
        }
    }
}

// ---------------- scan1: LIF hidden + fused sparse GEMM2 ------------------
// One thread per 4 (b,h) lanes; software-pipelined load (1-deep prefetch).
// On the (rare) spike, scatter W2 row into U2.   (exact R11 version)
__global__ void scan1_kernel(float4* __restrict__ out, const float* __restrict__ W2) {
    const int idx = blockIdx.x * blockDim.x + threadIdx.x;   // 0..65535
    const float4* u = reinterpret_cast<const float4*>(g_U1);
    const int j0 = idx * 4;
    const int b  = j0 >> 10;
    const int h0 = j0 & 1023;
    float4 mem = make_float4(0.f, 0.f, 0.f, 0.f);
    float4 vnext = __ldcg(&u[idx]);
#pragma unroll 4
    for (int t = 0; t < T_STEPS; t++) {
        float4 v = vnext;
        if (t + 1 < T_STEPS) vnext = __ldcg(&u[(size_t)(t + 1) * (BH / 4) + idx]);
        float4 s;
        mem.x = mem.x * DECAY + v.x; s.x = (mem.x >= THRESH) ? 1.f : 0.f; mem.x -= s.x * THRESH;
        mem.y = mem.y * DECAY + v.y; s.y = (mem.y >= THRESH) ? 1.f : 0.f; mem.y -= s.y * THRESH;
        mem.z = mem.z * DECAY + v.z; s.z = (mem.z >= THRESH) ? 1.f : 0.f; mem.z -= s.z * THRESH;
        mem.w = mem.w * DECAY + v.w; s.w = (mem.w >= THRESH) ? 1.f : 0.f; mem.w -= s.w * THRESH;
        out[(size_t)t * (BH / 4) + idx] = s;
        if (s.x + s.y + s.z + s.w > 0.f) {     // rare (~1900 spikes total)
            float sv[4] = {s.x, s.y, s.z, s.w};
            float* u2 = g_U2 + (size_t)(t * BATCH + b) * OUT_DIM;
#pragma unroll
            for (int q = 0; q < 4; q++) {
                if (sv[q] != 0.f) {
                    const float* w = W2 + (h0 + q) * OUT_DIM;
#pragma unroll
                    for (int o = 0; o < OUT_DIM; o++) atomicAdd(&u2[o], w[o]);
                }
            }
        }
    }
}

// ------------------------- scan2: cooperatively staged LIF output ---------
// 20 blocks x 512 threads; ALL 512 threads stage the [100][128] U2 slice
// (25 fully parallel coalesced loads each), then 128 threads scan from smem.
__global__ void scan2_kernel(float* __restrict__ out2) {
    extern __shared__ float sm[];                 // [100][128]
    const int tid = threadIdx.x;
    const int lane0 = blockIdx.x * 128;
#pragma unroll
    for (int i = tid; i < T_STEPS * 128; i += 512) {
        int t = i >> 7, lane = i & 127;
        sm[i] = g_U2[(size_t)t * BO + lane0 + lane];
    }
    __syncthreads();
    if (tid < 128) {
        float mem = 0.0f;
#pragma unroll 5
        for (int t = 0; t < T_STEPS; t++) {
            float u = sm[t * 128 + tid];
            mem = mem * DECAY + u;
            float s = (mem >= THRESH) ? 1.0f : 0.0f;
            mem -= s * THRESH;
            out2[(size_t)t * BO + lane0 + tid] = s;
        }
    }
}

// ------------------------- launch ------------------------------------------
extern "C" void kernel_launch(void* const* d_in, const int* in_sizes, int n_in,
                              void* d_out, int out_size) {
    const float* X  = (const float*)d_in[0];
    const float* W1 = (const float*)d_in[1];
    const float* W2 = (const float*)d_in[2];
    float* out = (float*)d_out;
    (void)in_sizes; (void)n_in; (void)out_size;

    static bool attr_done = false;
    if (!attr_done) {
        cudaFuncSetAttribute(gemm1_kernel, cudaFuncAttributeMaxDynamicSharedMemorySize, SMEM_TOTAL);
        cudaFuncSetAttribute(scan2_kernel, cudaFuncAttributeMaxDynamicSharedMemorySize, 51200);
        attr_done = true;
    }

    prep_kernel<<<PREPX_BLKS + PREPW_BLKS + ZERO_BLKS, 256>>>((const float4*)X, W1);

    gemm1_kernel<<<dim3(8, 200), 256, SMEM_TOTAL>>>();

    scan1_kernel<<<128, 512>>>((float4*)out, W2);

    scan2_kernel<<<20, 512, 51200>>>(out + HID_OUT);
}

// round 16
// speedup vs baseline: 1.0919x; 1.0538x over previous
#include <cuda_runtime.h>
#include <cuda_bf16.h>
#include <cstdint>
#include <cstddef>

// Problem dims (fixed)
#define T_STEPS 100
#define BATCH   256
#define IN_DIM  784
#define HID     1024
#define OUT_DIM 10
#define MROWS   25600
#define BH      262144
#define BO      2560
#define HID_OUT ((size_t)MROWS * HID)
#define THRESH 0.9f
#define DECAY  0.6f

// GEMM1 tiling: 128x128 CTA tile, BK=16, 49 k-iters, 6-stage cp.async ring
#define NKIT 49
#define NSTAGE 6
#define A_STAGE_B 6144u     // 128 rows * 24 bf16 (48B, padded)
#define B_PLANE_B 4352u     // 16 rows * 136 bf16 (272B, padded)
#define STAGE_B  14848u     // A + 2 B planes
#define SMEM_TOTAL (NSTAGE * STAGE_B)   // 89088 -> 2 CTAs/SM (178KB)

// ------------------------- scratch (device globals) -----------------------
__device__ __nv_bfloat16 g_Xbf[(size_t)MROWS * IN_DIM];        // 40.1 MB
__device__ __nv_bfloat16 g_W1c[(size_t)2 * IN_DIM * HID];      // hi rows 0..783, lo rows 784..1567
__device__ float         g_U1[(size_t)MROWS * HID];            // 104.9 MB
__device__ float         g_U2[(size_t)MROWS * OUT_DIM];        // 1.0 MB

// ------------------------- helpers ---------------------------------------
__device__ __forceinline__ uint32_t smem_u32(const void* p) {
    uint32_t a;
    asm("{ .reg .u64 t; cvta.to.shared.u64 t, %1; cvt.u32.u64 %0, t; }" : "=r"(a) : "l"(p));
    return a;
}
__device__ __forceinline__ void cpa16(uint32_t s, const void* g) {
    asm volatile("cp.async.cg.shared.global [%0], [%1], 16;\n" :: "r"(s), "l"(g));
}
__device__ __forceinline__ void ldsm_x4(uint32_t& r0, uint32_t& r1, uint32_t& r2, uint32_t& r3, uint32_t addr) {
    asm volatile("ldmatrix.sync.aligned.m8n8.x4.shared.b16 {%0,%1,%2,%3}, [%4];\n"
                 : "=r"(r0), "=r"(r1), "=r"(r2), "=r"(r3) : "r"(addr));
}
__device__ __forceinline__ void ldsm_x4_t(uint32_t& r0, uint32_t& r1, uint32_t& r2, uint32_t& r3, uint32_t addr) {
    asm volatile("ldmatrix.sync.aligned.m8n8.x4.trans.shared.b16 {%0,%1,%2,%3}, [%4];\n"
                 : "=r"(r0), "=r"(r1), "=r"(r2), "=r"(r3) : "r"(addr));
}
__device__ __forceinline__ void mma16816(float* c, const uint32_t* a, uint32_t b0, uint32_t b1) {
    asm volatile(
        "mma.sync.aligned.m16n8k16.row.col.f32.bf16.bf16.f32 "
        "{%0,%1,%2,%3}, {%4,%5,%6,%7}, {%8,%9}, {%0,%1,%2,%3};\n"
        : "+f"(c[0]), "+f"(c[1]), "+f"(c[2]), "+f"(c[3])
        : "r"(a[0]), "r"(a[1]), "r"(a[2]), "r"(a[3]), "r"(b0), "r"(b1));
}

// ------------------------- fused prep kernel -------------------------------
#define PREPX_BLKS 19600
#define PREPW_BLKS 3136
#define ZERO_BLKS  250
__global__ void prep_kernel(const float4* __restrict__ x, const float* __restrict__ w1) {
    const int bid = blockIdx.x;
    if (bid < PREPX_BLKS) {
        int i = bid * 256 + threadIdx.x;                  // < 5,017,600
        float4 v = x[i];
        __nv_bfloat162* dst = reinterpret_cast<__nv_bfloat162*>(g_Xbf);
        dst[2 * i]     = __floats2bfloat162_rn(v.x, v.y);
        dst[2 * i + 1] = __floats2bfloat162_rn(v.z, v.w);
    } else if (bid < PREPX_BLKS + PREPW_BLKS) {
        int i = (bid - PREPX_BLKS) * 256 + threadIdx.x;   // < 802816
        float w = w1[i];
        __nv_bfloat16 hi = __float2bfloat16(w);
        __nv_bfloat16 lo = __float2bfloat16(w - __bfloat162float(hi));
        g_W1c[i] = hi;
        g_W1c[802816 + i] = lo;
    } else {
        int i = (bid - PREPX_BLKS - PREPW_BLKS) * 256 + threadIdx.x;  // < 64000
        reinterpret_cast<float4*>(g_U2)[i] = make_float4(0.f, 0.f, 0.f, 0.f);
    }
}

// ------------------------- GEMM1: U1 = X @ (W1hi + W1lo) ------------------
// 8 warps (2x4), warp tile 64x32, fp32 accum; hi/lo passes share the A tile.
__global__ __launch_bounds__(256, 2) void gemm1_kernel() {
    extern __shared__ char smem[];
    const uint32_t sbase = smem_u32(smem);

    const int tid = threadIdx.x;
    const int bn0 = blockIdx.x * 128;
    const int bm0 = blockIdx.y * 128;

    const int lane   = tid & 31;
    const int wid    = tid >> 5;
    const int warp_m = wid >> 2;   // 0..1
    const int warp_n = wid & 3;    // 0..3

    float acc[4][4][4];
#pragma unroll
    for (int i = 0; i < 4; i++)
#pragma unroll
        for (int j = 0; j < 4; j++)
#pragma unroll
            for (int k = 0; k < 4; k++) acc[i][j][k] = 0.0f;

    // producer addressing
    const int arow = tid >> 1, ach = tid & 1;
    const __nv_bfloat16* agp = g_Xbf + (size_t)(bm0 + arow) * IN_DIM + ach * 8;
    const int brow = tid >> 4, bch = tid & 15;
    const __nv_bfloat16* bgp = g_W1c + (size_t)brow * HID + bn0 + bch * 8;

    const uint32_t a_dst = sbase + arow * 48 + ach * 16;
    const uint32_t b_dst = sbase + A_STAGE_B + brow * 272 + bch * 16;

#define LOAD_STAGE(slot, kt) do {                                                   \
        uint32_t so = (slot) * STAGE_B;                                             \
        const __nv_bfloat16* a = agp + (size_t)(kt) * 16;                           \
        const __nv_bfloat16* b = bgp + (size_t)(kt) * 16 * HID;                     \
        cpa16(a_dst + so, a);                                                       \
        cpa16(b_dst + so, b);                                                       \
        cpa16(b_dst + so + B_PLANE_B, b + 802816);                                  \
        asm volatile("cp.async.commit_group;\n" ::: "memory");                      \
    } while (0)

    LOAD_STAGE(0, 0);
    LOAD_STAGE(1, 1);
    LOAD_STAGE(2, 2);
    LOAD_STAGE(3, 3);
    LOAD_STAGE(4, 4);

    for (int kt = 0; kt < NKIT; kt++) {
        const int cur = kt % NSTAGE;
        asm volatile("cp.async.wait_group 4;\n" ::: "memory");
        __syncthreads();

        // prefetch 5 ahead into the slot consumed last iteration
        if (kt + 5 < NKIT) {
            LOAD_STAGE((kt + 5) % NSTAGE, kt + 5);
        } else {
            asm volatile("cp.async.commit_group;\n" ::: "memory");
        }

        const uint32_t so = sbase + cur * STAGE_B;

        // A fragments (shared by hi/lo passes)
        uint32_t a[4][4];
#pragma unroll
        for (int mt = 0; mt < 4; mt++) {
            int row = warp_m * 64 + mt * 16 + (lane & 15);
            uint32_t addr = so + row * 48 + (lane >> 4) * 16;
            ldsm_x4(a[mt][0], a[mt][1], a[mt][2], a[mt][3], addr);
        }
#pragma unroll
        for (int p = 0; p < 2; p++) {
            // hoist both B ldsm of this pass before the 16 MMAs
            uint32_t b[2][4];
#pragma unroll
            for (int nt = 0; nt < 2; nt++) {
                int krow = lane & 15;
                int col  = warp_n * 32 + nt * 16 + (lane >> 4) * 8;
                uint32_t addr = so + A_STAGE_B + p * B_PLANE_B + krow * 272 + col * 2;
                ldsm_x4_t(b[nt][0], b[nt][1], b[nt][2], b[nt][3], addr);
            }
#pragma unroll
            for (int nt = 0; nt < 2; nt++) {
#pragma unroll
                for (int mt = 0; mt < 4; mt++) {
                    mma16816(acc[mt][nt * 2],     a[mt], b[nt][0], b[nt][1]);
                    mma16816(acc[mt][nt * 2 + 1], a[mt], b[nt][2], b[nt][3]);
                }
            }
        }
    }
#undef LOAD_STAGE

    // epilogue: write U1 (fp32)
    const int g  = lane >> 2;
    const int tg = lane & 3;
#pragma unroll
    for (int mt = 0; mt < 4; mt++) {
        int m0 = bm0 + warp_m * 64 + mt * 16 + g;
#pragma unroll
        for (int nf = 0; nf < 4; nf++) {
            int n0 = bn0 + warp_n * 32 + nf * 8 + tg * 2;
            float2 v0 = make_float2(acc[mt][nf][0], acc[mt][nf][1]);
            float2 v1 = make_float2(acc[mt][nf][2], acc[mt][nf][3]);
            *(float2*)&g_U1[(size_t)m0 * HID + n0]       = v0;
            *(float2*)&g_U1[(size_t)(m0 + 8) * HID + n0] = v1;
        }
    }
}

// ---------------- scan1: LIF hidden + fused sparse GEMM2 ------------------
// One thread per 4 (b,h) lanes; software-pipelined load (1-deep prefetch).
// On the (rare) spike, scatter W2 row into U2.
__global__ void scan1_kernel(float4* __restrict__ out, const float* __restrict__ W2) {
    const int idx = blockIdx.x * blockDim.x + threadIdx.x;   // 0..65535
    const float4* u = reinterpret_cast<const float4*>(g_U1);
    const int j0 = idx * 4;
    const int b  = j0 >> 10;
    const int h0 = j0 & 1023;
    float4 mem = make_float4(0.f, 0.f, 0.f, 0.f);
    float4 vnext = __ldcg(&u[idx]);
#pragma unroll 4
    for (int t = 0; t < T_STEPS; t++) {
        float4 v = vnext;
        if (t + 1 < T_STEPS) vnext = __ldcg(&u[(size_t)(t + 1) * (BH / 4) + idx]);
        float4 s;
        mem.x = mem.x * DECAY + v.x; s.x = (mem.x >= THRESH) ? 1.f : 0.f; mem.x -= s.x * THRESH;
        mem.y = mem.y * DECAY + v.y; s.y = (mem.y >= THRESH) ? 1.f : 0.f; mem.y -= s.y * THRESH;
        mem.z = mem.z * DECAY + v.z; s.z = (mem.z >= THRESH) ? 1.f : 0.f; mem.z -= s.z * THRESH;
        mem.w = mem.w * DECAY + v.w; s.w = (mem.w >= THRESH) ? 1.f : 0.f; mem.w -= s.w * THRESH;
        out[(size_t)t * (BH / 4) + idx] = s;
        if (s.x + s.y + s.z + s.w > 0.f) {     // rare (~1900 spikes total)
            float sv[4] = {s.x, s.y, s.z, s.w};
            float* u2 = g_U2 + (size_t)(t * BATCH + b) * OUT_DIM;
#pragma unroll
            for (int q = 0; q < 4; q++) {
                if (sv[q] != 0.f) {
                    const float* w = W2 + (h0 + q) * OUT_DIM;
#pragma unroll
                    for (int o = 0; o < OUT_DIM; o++) atomicAdd(&u2[o], w[o]);
                }
            }
        }
    }
}

// ------------------------- scan2: cooperatively staged LIF output ---------
// 20 blocks x 512 threads; ALL 512 threads stage the [100][128] U2 slice
// (25 fully parallel coalesced loads each), then 128 threads scan from smem.
__global__ void scan2_kernel(float* __restrict__ out2) {
    extern __shared__ float sm[];                 // [100][128]
    const int tid = threadIdx.x;
    const int lane0 = blockIdx.x * 128;
#pragma unroll
    for (int i = tid; i < T_STEPS * 128; i += 512) {
        int t = i >> 7, lane = i & 127;
        sm[i] = g_U2[(size_t)t * BO + lane0 + lane];
    }
    __syncthreads();
    if (tid < 128) {
        float mem = 0.0f;
#pragma unroll 5
        for (int t = 0; t < T_STEPS; t++) {
            float u = sm[t * 128 + tid];
            mem = mem * DECAY + u;
            float s = (mem >= THRESH) ? 1.0f : 0.0f;
            mem -= s * THRESH;
            out2[(size_t)t * BO + lane0 + tid] = s;
        }
    }
}

// ------------------------- launch ------------------------------------------
extern "C" void kernel_launch(void* const* d_in, const int* in_sizes, int n_in,
                              void* d_out, int out_size) {
    const float* X  = (const float*)d_in[0];
    const float* W1 = (const float*)d_in[1];
    const float* W2 = (const float*)d_in[2];
    float* out = (float*)d_out;
    (void)in_sizes; (void)n_in; (void)out_size;

    static bool attr_done = false;
    if (!attr_done) {
        cudaFuncSetAttribute(gemm1_kernel, cudaFuncAttributeMaxDynamicSharedMemorySize, SMEM_TOTAL);
        cudaFuncSetAttribute(scan2_kernel, cudaFuncAttributeMaxDynamicSharedMemorySize, 51200);
        attr_done = true;
    }

    prep_kernel<<<PREPX_BLKS + PREPW_BLKS + ZERO_BLKS, 256>>>((const float4*)X, W1);

    gemm1_kernel<<<dim3(8, 200), 256, SMEM_TOTAL>>>();

    scan1_kernel<<<128, 512>>>((float4*)out, W2);

    scan2_kernel<<<20, 512, 51200>>>(out + HID_OUT);
}

// round 17
// speedup vs baseline: 1.1028x; 1.0100x over previous
#include <cuda_runtime.h>
#include <cuda_bf16.h>
#include <cstdint>
#include <cstddef>

// Problem dims (fixed)
#define T_STEPS 100
#define BATCH   256
#define IN_DIM  784
#define HID     1024
#define OUT_DIM 10
#define MROWS   25600
#define BH      262144
#define BO      2560
#define HID_OUT ((size_t)MROWS * HID)
#define THRESH 0.9f
#define DECAY  0.6f

// GEMM1: 128x128 CTA tile, BK=16, 49 k-iters.
// A is bit-packed (X in {0,1}): staged once per CTA (12.5KB), expanded to bf16
// in-smem one slab ahead. B (hi+lo bf16 planes) uses the proven 6-stage
// cp.async ring, prefetch 5 ahead, wait_group 4.
#define NKIT 49
#define NSTAGE 6
#define ROWBITS_B 98u                       // 784/8 bytes per row
#define BITS_B    12544u                    // 128 rows * 98
#define A_BUF_B   6144u                     // 128 rows * 48B (16 bf16 padded)
#define ABASE     BITS_B                    // after bits
#define BBASE     (BITS_B + 2u * A_BUF_B)   // 24832
#define B_PLANE_B 4352u                     // 16 rows * 272B (128 bf16 padded)
#define B_STAGE_B (2u * B_PLANE_B)          // 8704
#define SMEM_TOTAL (BBASE + NSTAGE * B_STAGE_B)   // 77056 -> 2 CTAs/SM (154KB)

// ------------------------- scratch (device globals) -----------------------
__device__ uint8_t       g_Xbits[(size_t)MROWS * ROWBITS_B];   // 2.5 MB
__device__ __nv_bfloat16 g_W1c[(size_t)2 * IN_DIM * HID];      // hi | lo planes
__device__ float         g_U1[(size_t)MROWS * HID];            // 104.9 MB
__device__ float         g_U2[(size_t)MROWS * OUT_DIM];        // 1.0 MB

// ------------------------- helpers ---------------------------------------
__device__ __forceinline__ uint32_t smem_u32(const void* p) {
    uint32_t a;
    asm("{ .reg .u64 t; cvta.to.shared.u64 t, %1; cvt.u32.u64 %0, t; }" : "=r"(a) : "l"(p));
    return a;
}
__device__ __forceinline__ void cpa16(uint32_t s, const void* g) {
    asm volatile("cp.async.cg.shared.global [%0], [%1], 16;\n" :: "r"(s), "l"(g));
}
__device__ __forceinline__ void ldsm_x4(uint32_t& r0, uint32_t& r1, uint32_t& r2, uint32_t& r3, uint32_t addr) {
    asm volatile("ldmatrix.sync.aligned.m8n8.x4.shared.b16 {%0,%1,%2,%3}, [%4];\n"
                 : "=r"(r0), "=r"(r1), "=r"(r2), "=r"(r3) : "r"(addr));
}
__device__ __forceinline__ void ldsm_x4_t(uint32_t& r0, uint32_t& r1, uint32_t& r2, uint32_t& r3, uint32_t addr) {
    asm volatile("ldmatrix.sync.aligned.m8n8.x4.trans.shared.b16 {%0,%1,%2,%3}, [%4];\n"
                 : "=r"(r0), "=r"(r1), "=r"(r2), "=r"(r3) : "r"(addr));
}
__device__ __forceinline__ void mma16816(float* c, const uint32_t* a, uint32_t b0, uint32_t b1) {
    asm volatile(
        "mma.sync.aligned.m16n8k16.row.col.f32.bf16.bf16.f32 "
        "{%0,%1,%2,%3}, {%4,%5,%6,%7}, {%8,%9}, {%0,%1,%2,%3};\n"
        : "+f"(c[0]), "+f"(c[1]), "+f"(c[2]), "+f"(c[3])
        : "r"(a[0]), "r"(a[1]), "r"(a[2]), "r"(a[3]), "r"(b0), "r"(b1));
}

// ------------------------- fused prep kernel -------------------------------
// Blocks [0, 4900): X fp32 -> bitmask (16 cols -> uint16 per thread)
// Blocks [4900, 8036): W1 split hi/lo bf16 planes
// Blocks [8036, 8286): zero U2
#define PREPX_BLKS 4900
#define PREPW_BLKS 3136
#define ZERO_BLKS  250
__global__ void prep_kernel(const float* __restrict__ x, const float* __restrict__ w1) {
    const int bid = blockIdx.x;
    if (bid < PREPX_BLKS) {
        int i = bid * 256 + threadIdx.x;                  // < 1,254,400
        int row = i / 49, c16 = i % 49;
        const float4* s4 = (const float4*)(x + (size_t)row * IN_DIM + c16 * 16);
        uint32_t m = 0;
#pragma unroll
        for (int j = 0; j < 4; j++) {
            float4 v = s4[j];
            m |= (v.x != 0.f ? 1u : 0u) << (4 * j);
            m |= (v.y != 0.f ? 2u : 0u) << (4 * j);
            m |= (v.z != 0.f ? 4u : 0u) << (4 * j);
            m |= (v.w != 0.f ? 8u : 0u) << (4 * j);
        }
        *reinterpret_cast<uint16_t*>(g_Xbits + (size_t)row * ROWBITS_B + c16 * 2) = (uint16_t)m;
    } else if (bid < PREPX_BLKS + PREPW_BLKS) {
        int i = (bid - PREPX_BLKS) * 256 + threadIdx.x;   // < 802816
        float w = w1[i];
        __nv_bfloat16 hi = __float2bfloat16(w);
        __nv_bfloat16 lo = __float2bfloat16(w - __bfloat162float(hi));
        g_W1c[i] = hi;
        g_W1c[802816 + i] = lo;
    } else {
        int i = (bid - PREPX_BLKS - PREPW_BLKS) * 256 + threadIdx.x;  // < 64000
        reinterpret_cast<float4*>(g_U2)[i] = make_float4(0.f, 0.f, 0.f, 0.f);
    }
}

// ------------------------- GEMM1: U1 = X @ (W1hi + W1lo) ------------------
// 8 warps (2x4), warp tile 64x32, fp32 accum; hi/lo passes share the A tile.
// A expanded from bits one slab ahead (ping-pong); B via 6-stage cp.async ring.
__global__ __launch_bounds__(256, 2) void gemm1_kernel() {
    extern __shared__ char smem[];
    const uint32_t sbase = smem_u32(smem);

    const int tid = threadIdx.x;
    const int bn0 = blockIdx.x * 128;
    const int bm0 = blockIdx.y * 128;

    const int lane   = tid & 31;
    const int wid    = tid >> 5;
    const int warp_m = wid >> 2;   // 0..1
    const int warp_n = wid & 3;    // 0..3

    float acc[4][4][4];
#pragma unroll
    for (int i = 0; i < 4; i++)
#pragma unroll
        for (int j = 0; j < 4; j++)
#pragma unroll
            for (int k = 0; k < 4; k++) acc[i][j][k] = 0.0f;

    // B producer addressing (unchanged from champion)
    const int brow = tid >> 4, bch = tid & 15;
    const __nv_bfloat16* bgp = g_W1c + (size_t)brow * HID + bn0 + bch * 8;
    const uint32_t b_dst = sbase + BBASE + brow * 272 + bch * 16;

    // A expansion addressing: thread -> row r, half h (8 cols = 1 byte of bits)
    const int ar = tid >> 1, ah = tid & 1;
    const uint8_t* sbits = reinterpret_cast<const uint8_t*>(smem);
    uint4* const abuf0 = reinterpret_cast<uint4*>(smem + ABASE + ar * 48 + ah * 16);
    uint4* const abuf1 = reinterpret_cast<uint4*>(smem + ABASE + A_BUF_B + ar * 48 + ah * 16);

#define EXPAND_A(kt) do {                                                           \
        uint32_t bits = sbits[ar * ROWBITS_B + (kt) * 2 + ah];                      \
        uint4 w;                                                                    \
        w.x = ((bits & 1u)   ? 0x3F80u : 0u) | ((bits & 2u)   ? 0x3F800000u : 0u);  \
        w.y = ((bits & 4u)   ? 0x3F80u : 0u) | ((bits & 8u)   ? 0x3F800000u : 0u);  \
        w.z = ((bits & 16u)  ? 0x3F80u : 0u) | ((bits & 32u)  ? 0x3F800000u : 0u);  \
        w.w = ((bits & 64u)  ? 0x3F80u : 0u) | ((bits & 128u) ? 0x3F800000u : 0u);  \
        if ((kt) & 1) *abuf1 = w; else *abuf0 = w;                                  \
    } while (0)

#define LOAD_B(slot, kt) do {                                                       \
        uint32_t so = BBASE + (slot) * B_STAGE_B;                                   \
        const __nv_bfloat16* b = bgp + (size_t)(kt) * 16 * HID;                     \
        cpa16(sbase + (so - BBASE) + b_dst - sbase + 0, b);                         \
        cpa16(b_dst - BBASE * 0 + (so - BBASE) + B_PLANE_B, b + 802816);            \
        asm volatile("cp.async.commit_group;\n" ::: "memory");                      \
    } while (0)
#undef LOAD_B
#define LOAD_B(slot, kt) do {                                                       \
        uint32_t so = (slot) * B_STAGE_B;                                           \
        const __nv_bfloat16* b = bgp + (size_t)(kt) * 16 * HID;                     \
        cpa16(b_dst + so, b);                                                       \
        cpa16(b_dst + so + B_PLANE_B, b + 802816);                                  \
        asm volatile("cp.async.commit_group;\n" ::: "memory");                      \
    } while (0)

    // stage this CTA's bit-block (12544B contiguous, 16B-aligned)
    {
        const uint4* gb = reinterpret_cast<const uint4*>(g_Xbits + (size_t)bm0 * ROWBITS_B);
        uint4* sb = reinterpret_cast<uint4*>(smem);
#pragma unroll
        for (int i = tid; i < 784; i += 256) sb[i] = gb[i];
    }

    LOAD_B(0, 0);
    LOAD_B(1, 1);
    LOAD_B(2, 2);
    LOAD_B(3, 3);
    LOAD_B(4, 4);

    __syncthreads();          // bits visible to all threads
    EXPAND_A(0);              // slab 0 into abuf0 (visible after iter-0 sync)

    for (int kt = 0; kt < NKIT; kt++) {
        const int cur = kt % NSTAGE;
        asm volatile("cp.async.wait_group 4;\n" ::: "memory");
        __syncthreads();

        // prefetch B 5 ahead
        if (kt + 5 < NKIT) {
            LOAD_B((kt + 5) % NSTAGE, kt + 5);
        } else {
            asm volatile("cp.async.commit_group;\n" ::: "memory");
        }

        // expand A for next slab into the other buffer (ordered by next sync)
        if (kt + 1 < NKIT) EXPAND_A(kt + 1);

        const uint32_t aso = sbase + ABASE + (kt & 1) * A_BUF_B;
        const uint32_t bso = sbase + BBASE + cur * B_STAGE_B;

        // A fragments (shared by hi/lo passes)
        uint32_t a[4][4];
#pragma unroll
        for (int mt = 0; mt < 4; mt++) {
            int row = warp_m * 64 + mt * 16 + (lane & 15);
            uint32_t addr = aso + row * 48 + (lane >> 4) * 16;
            ldsm_x4(a[mt][0], a[mt][1], a[mt][2], a[mt][3], addr);
        }
#pragma unroll
        for (int p = 0; p < 2; p++) {
            uint32_t b[2][4];
#pragma unroll
            for (int nt = 0; nt < 2; nt++) {
                int krow = lane & 15;
                int col  = warp_n * 32 + nt * 16 + (lane >> 4) * 8;
                uint32_t addr = bso + p * B_PLANE_B + krow * 272 + col * 2;
                ldsm_x4_t(b[nt][0], b[nt][1], b[nt][2], b[nt][3], addr);
            }
#pragma unroll
            for (int nt = 0; nt < 2; nt++) {
#pragma unroll
                for (int mt = 0; mt < 4; mt++) {
                    mma16816(acc[mt][nt * 2],     a[mt], b[nt][0], b[nt][1]);
                    mma16816(acc[mt][nt * 2 + 1], a[mt], b[nt][2], b[nt][3]);
                }
            }
        }
    }
#undef LOAD_B
#undef EXPAND_A

    // epilogue: write U1 (fp32)
    const int g  = lane >> 2;
    const int tg = lane & 3;
#pragma unroll
    for (int mt = 0; mt < 4; mt++) {
        int m0 = bm0 + warp_m * 64 + mt * 16 + g;
#pragma unroll
        for (int nf = 0; nf < 4; nf++) {
            int n0 = bn0 + warp_n * 32 + nf * 8 + tg * 2;
            float2 v0 = make_float2(acc[mt][nf][0], acc[mt][nf][1]);
            float2 v1 = make_float2(acc[mt][nf][2], acc[mt][nf][3]);
            *(float2*)&g_U1[(size_t)m0 * HID + n0]       = v0;
            *(float2*)&g_U1[(size_t)(m0 + 8) * HID + n0] = v1;
        }
    }
}

// ---------------- scan1: LIF hidden + fused sparse GEMM2 ------------------
// One thread per 4 (b,h) lanes; software-pipelined load (1-deep prefetch).
// On the (rare) spike, scatter W2 row into U2.
__global__ void scan1_kernel(float4* __restrict__ out, const float* __restrict__ W2) {
    const int idx = blockIdx.x * blockDim.x + threadIdx.x;   // 0..65535
    const float4* u = reinterpret_cast<const float4*>(g_U1);
    const int j0 = idx * 4;
    const int b  = j0 >> 10;
    const int h0 = j0 & 1023;
    float4 mem = make_float4(0.f, 0.f, 0.f, 0.f);
    float4 vnext = __ldcg(&u[idx]);
#pragma unroll 4
    for (int t = 0; t < T_STEPS; t++) {
        float4 v = vnext;
        if (t + 1 < T_STEPS) vnext = __ldcg(&u[(size_t)(t + 1) * (BH / 4) + idx]);
        float4 s;
        mem.x = mem.x * DECAY + v.x; s.x = (mem.x >= THRESH) ? 1.f : 0.f; mem.x -= s.x * THRESH;
        mem.y = mem.y * DECAY + v.y; s.y = (mem.y >= THRESH) ? 1.f : 0.f; mem.y -= s.y * THRESH;
        mem.z = mem.z * DECAY + v.z; s.z = (mem.z >= THRESH) ? 1.f : 0.f; mem.z -= s.z * THRESH;
        mem.w = mem.w * DECAY + v.w; s.w = (mem.w >= THRESH) ? 1.f : 0.f; mem.w -= s.w * THRESH;
        out[(size_t)t * (BH / 4) + idx] = s;
        if (s.x + s.y + s.z + s.w > 0.f) {     // rare (~1900 spikes total)
            float sv[4] = {s.x, s.y, s.z, s.w};
            float* u2 = g_U2 + (size_t)(t * BATCH + b) * OUT_DIM;
#pragma unroll
            for (int q = 0; q < 4; q++) {
                if (sv[q] != 0.f) {
                    const float* w = W2 + (h0 + q) * OUT_DIM;
#pragma unroll
                    for (int o = 0; o < OUT_DIM; o++) atomicAdd(&u2[o], w[o]);
                }
            }
        }
    }
}

// ------------------------- scan2: cooperatively staged LIF output ---------
__global__ void scan2_kernel(float* __restrict__ out2) {
    extern __shared__ float sm[];                 // [100][128]
    const int tid = threadIdx.x;
    const int lane0 = blockIdx.x * 128;
#pragma unroll
    for (int i = tid; i < T_STEPS * 128; i += 512) {
        int t = i >> 7, lane = i & 127;
        sm[i] = g_U2[(size_t)t * BO + lane0 + lane];
    }
    __syncthreads();
    if (tid < 128) {
        float mem = 0.0f;
#pragma unroll 5
        for (int t = 0; t < T_STEPS; t++) {
            float u = sm[t * 128 + tid];
            mem = mem * DECAY + u;
            float s = (mem >= THRESH) ? 1.0f : 0.0f;
            mem -= s * THRESH;
            out2[(size_t)t * BO + lane0 + tid] = s;
        }
    }
}

// ------------------------- launch ------------------------------------------
extern "C" void kernel_launch(void* const* d_in, const int* in_sizes, int n_in,
                              void* d_out, int out_size) {
    const float* X  = (const float*)d_in[0];
    const float* W1 = (const float*)d_in[1];
    const float* W2 = (const float*)d_in[2];
    float* out = (float*)d_out;
    (void)in_sizes; (void)n_in; (void)out_size;

    static bool attr_done = false;
    if (!attr_done) {
        cudaFuncSetAttribute(gemm1_kernel, cudaFuncAttributeMaxDynamicSharedMemorySize, SMEM_TOTAL);
        cudaFuncSetAttribute(scan2_kernel, cudaFuncAttributeMaxDynamicSharedMemorySize, 51200);
        attr_done = true;
    }

    prep_kernel<<<PREPX_BLKS + PREPW_BLKS + ZERO_BLKS, 256>>>(X, W1);

    gemm1_kernel<<<dim3(8, 200), 256, SMEM_TOTAL>>>();

    scan1_kernel<<<128, 512>>>((float4*)out, W2);

    scan2_kernel<<<20, 512, 51200>>>(out + HID_OUT);
}